// round 15
// baseline (speedup 1.0000x reference)
#include <cuda_runtime.h>
#include <cuda_fp16.h>
#include <cstddef>
#include <cstdint>

#define NMAX 100000
#define EMAX 1600000
#define DHC  128

// Scratch (static __device__ arrays; no allocation allowed)
__device__ float  g_dinv[NMAX];
__device__ int    g_deg[NMAX];
__device__ int    g_offs[NMAX + 1];
__device__ int    g_csr[EMAX];
__device__ int    g_bsum[1024];
__device__ __half g_hs[(size_t)NMAX * DHC];
__device__ __half g_h [(size_t)NMAX * DHC];
__device__ __half g_z [(size_t)NMAX * DHC];

// ---------------------------------------------------------------------------
// Degree histogram (int)
// ---------------------------------------------------------------------------
__global__ void deg_kernel(const int* __restrict__ ei, int* __restrict__ deg, int E) {
    int i = blockIdx.x * blockDim.x + threadIdx.x;
    int stride = gridDim.x * blockDim.x;
    for (; i < E; i += stride)
        atomicAdd(&deg[ei[E + i]], 1);
}

// ---------------------------------------------------------------------------
// Scan phase 1: per-block inclusive scan -> exclusive offs + block sums
// ---------------------------------------------------------------------------
__global__ void scan_phase1(const int* __restrict__ deg, int* __restrict__ offs,
                            int* __restrict__ bsum, int n) {
    __shared__ int sh[1024];
    int i = blockIdx.x * 1024 + threadIdx.x;
    int v = (i < n) ? deg[i] : 0;
    sh[threadIdx.x] = v;
    __syncthreads();
    for (int d = 1; d < 1024; d <<= 1) {
        int t = (threadIdx.x >= d) ? sh[threadIdx.x - d] : 0;
        __syncthreads();
        sh[threadIdx.x] += t;
        __syncthreads();
    }
    if (i < n) offs[i] = sh[threadIdx.x] - v;   // exclusive within block
    if (threadIdx.x == 1023) bsum[blockIdx.x] = sh[1023];
}

// ---------------------------------------------------------------------------
// Scan phase 3b: each block REDUNDANTLY scans bsum (nb <= 1024), adds its
// block prefix, emits dinv, and writes offs[n] = E sentinel.
// ---------------------------------------------------------------------------
__global__ void scan_phase3b(int* __restrict__ offs, const int* __restrict__ bsum,
                             int nb, const int* __restrict__ deg,
                             float* __restrict__ dinv, int n) {
    __shared__ int sh[1024];
    int v = (threadIdx.x < nb) ? bsum[threadIdx.x] : 0;
    sh[threadIdx.x] = v;
    __syncthreads();
    for (int d = 1; d < 1024; d <<= 1) {
        int t = (threadIdx.x >= d) ? sh[threadIdx.x - d] : 0;
        __syncthreads();
        sh[threadIdx.x] += t;
        __syncthreads();
    }
    int excl = (blockIdx.x == 0) ? 0 : sh[blockIdx.x - 1];
    int i = blockIdx.x * 1024 + threadIdx.x;
    if (i < n) {
        int o = offs[i] + excl;
        offs[i] = o;
        int dg = deg[i];
        dinv[i] = rsqrtf((float)dg + 1.0f);
        if (i == n - 1) offs[n] = o + dg;
    }
}

// ---------------------------------------------------------------------------
// CSR fill: countdown on deg (deg ends at 0; gather uses offs diffs)
// ---------------------------------------------------------------------------
__global__ void fill_kernel(const int* __restrict__ ei, const int* __restrict__ offs,
                            int* __restrict__ deg, int* __restrict__ csr, int E) {
    int i = blockIdx.x * blockDim.x + threadIdx.x;
    int stride = gridDim.x * blockDim.x;
    for (; i < E; i += stride) {
        int src = ei[i];
        int dst = ei[E + i];
        int pos = offs[dst] + atomicSub(&deg[dst], 1) - 1;
        csr[pos] = src;
    }
}

// ---------------------------------------------------------------------------
// TF32 tensor-core GEMM: out_fp16[r,:] = A[r,:K] @ W[K,128]
// fp32 inputs go through cvt.rna.tf32 (unbiased rounding — REQUIRED: raw-bit
// truncation is biased and accumulates ~1e-3 error over K=256).
// fp16 A (AHALF=true) is exact in tf32, no rounding needed.
// BM=128 BN=128 BK=16, 256 threads = 8 warps (4x2), warp tile 32x64.
// ---------------------------------------------------------------------------
__device__ __forceinline__ uint32_t f2tf32(float x) {
    uint32_t r;
    asm("cvt.rna.tf32.f32 %0, %1;" : "=r"(r) : "f"(x));
    return r;
}

template<bool AHALF>
__global__ __launch_bounds__(256, 2) void gemm_tf32_kernel(
    const void* __restrict__ Av, const float* __restrict__ W,
    __half* __restrict__ out, int M, int K)
{
    constexpr int BM = 128, BN = 128, BK = 16;
    constexpr int ASTR = BK + 4;   // 20
    constexpr int BSTR = BN + 8;   // 136
    __shared__ uint32_t As[BM * ASTR];
    __shared__ uint32_t Bs[BK * BSTR];

    const int tid  = threadIdx.x;
    const int wid  = tid >> 5;
    const int lane = tid & 31;
    const int g    = lane >> 2;
    const int t    = lane & 3;
    const int warpM = wid >> 1;
    const int warpN = wid & 1;
    const int row0 = blockIdx.x * BM;

    // fp32-A load map: 512 float4/tile (128 rows x 4 float4), 2 per thread
    const int ar0 = tid >> 2;            // 0..63
    const int ac0 = (tid & 3) * 4;       // 0,4,8,12
    const int ar1 = ar0 + 64;            // 64..127
    // fp16-A load map: 256 uint4/tile, 1 per thread
    const int arh = tid >> 1, ach = (tid & 1) * 8;
    // B load map
    const int br0 = wid, br1 = wid + 8;
    const int bc  = lane * 4;

    float acc[2][8][4];
#pragma unroll
    for (int mi = 0; mi < 2; mi++)
#pragma unroll
        for (int ni = 0; ni < 8; ni++)
#pragma unroll
            for (int c = 0; c < 4; c++) acc[mi][ni][c] = 0.0f;

    float4 aPre0, aPre1, bPre0, bPre1;
    uint4  aPreH;
    {
        if (AHALF) {
            const __half* A = (const __half*)Av;
            int r = row0 + arh;
            aPreH = (r < M) ? *reinterpret_cast<const uint4*>(A + (size_t)r * K + ach)
                            : make_uint4(0, 0, 0, 0);
        } else {
            const float* A = (const float*)Av;
            int r = row0 + ar0;
            aPre0 = (r < M) ? *reinterpret_cast<const float4*>(A + (size_t)r * K + ac0)
                            : make_float4(0.f, 0.f, 0.f, 0.f);
            r = row0 + ar1;
            aPre1 = (r < M) ? *reinterpret_cast<const float4*>(A + (size_t)r * K + ac0)
                            : make_float4(0.f, 0.f, 0.f, 0.f);
        }
        bPre0 = *reinterpret_cast<const float4*>(W + (size_t)br0 * BN + bc);
        bPre1 = *reinterpret_cast<const float4*>(W + (size_t)br1 * BN + bc);
    }

    const int mBase = warpM * 32;
    const int nBase = warpN * 64;

    for (int k0 = 0; k0 < K; k0 += BK) {
        if (AHALF) {
            // fp16 -> fp32 is exact, and fp16 values fit tf32 exactly: raw bits OK
            uint32_t* p = &As[arh * ASTR + ach];
            const __half2* hp = reinterpret_cast<const __half2*>(&aPreH);
#pragma unroll
            for (int q = 0; q < 4; q++) {
                float2 f = __half22float2(hp[q]);
                p[2 * q    ] = __float_as_uint(f.x);
                p[2 * q + 1] = __float_as_uint(f.y);
            }
        } else {
            uint32_t* p = &As[ar0 * ASTR + ac0];
            p[0] = f2tf32(aPre0.x); p[1] = f2tf32(aPre0.y);
            p[2] = f2tf32(aPre0.z); p[3] = f2tf32(aPre0.w);
            p = &As[ar1 * ASTR + ac0];
            p[0] = f2tf32(aPre1.x); p[1] = f2tf32(aPre1.y);
            p[2] = f2tf32(aPre1.z); p[3] = f2tf32(aPre1.w);
        }
        {
            uint32_t* p = &Bs[br0 * BSTR + bc];
            p[0] = f2tf32(bPre0.x); p[1] = f2tf32(bPre0.y);
            p[2] = f2tf32(bPre0.z); p[3] = f2tf32(bPre0.w);
            p = &Bs[br1 * BSTR + bc];
            p[0] = f2tf32(bPre1.x); p[1] = f2tf32(bPre1.y);
            p[2] = f2tf32(bPre1.z); p[3] = f2tf32(bPre1.w);
        }
        __syncthreads();

        if (k0 + BK < K) {
            int kn = k0 + BK;
            if (AHALF) {
                const __half* A = (const __half*)Av;
                int r = row0 + arh;
                aPreH = (r < M) ? *reinterpret_cast<const uint4*>(A + (size_t)r * K + kn + ach)
                                : make_uint4(0, 0, 0, 0);
            } else {
                const float* A = (const float*)Av;
                int r = row0 + ar0;
                aPre0 = (r < M) ? *reinterpret_cast<const float4*>(A + (size_t)r * K + kn + ac0)
                                : make_float4(0.f, 0.f, 0.f, 0.f);
                r = row0 + ar1;
                aPre1 = (r < M) ? *reinterpret_cast<const float4*>(A + (size_t)r * K + kn + ac0)
                                : make_float4(0.f, 0.f, 0.f, 0.f);
            }
            bPre0 = *reinterpret_cast<const float4*>(W + (size_t)(kn + br0) * BN + bc);
            bPre1 = *reinterpret_cast<const float4*>(W + (size_t)(kn + br1) * BN + bc);
        }

#pragma unroll
        for (int ks = 0; ks < 2; ks++) {
            const int kb = ks * 8;
            uint32_t af[2][4];
#pragma unroll
            for (int mi = 0; mi < 2; mi++) {
                int m = mBase + mi * 16 + g;
                af[mi][0] = As[(m    ) * ASTR + kb + t];
                af[mi][1] = As[(m + 8) * ASTR + kb + t];
                af[mi][2] = As[(m    ) * ASTR + kb + t + 4];
                af[mi][3] = As[(m + 8) * ASTR + kb + t + 4];
            }
            uint32_t bf[8][2];
#pragma unroll
            for (int ni = 0; ni < 8; ni++) {
                int n = nBase + ni * 8 + g;
                bf[ni][0] = Bs[(kb + t    ) * BSTR + n];
                bf[ni][1] = Bs[(kb + t + 4) * BSTR + n];
            }
#pragma unroll
            for (int mi = 0; mi < 2; mi++)
#pragma unroll
                for (int ni = 0; ni < 8; ni++) {
                    asm volatile(
                        "mma.sync.aligned.m16n8k8.row.col.f32.tf32.tf32.f32 "
                        "{%0,%1,%2,%3}, {%4,%5,%6,%7}, {%8,%9}, {%0,%1,%2,%3};"
                        : "+f"(acc[mi][ni][0]), "+f"(acc[mi][ni][1]),
                          "+f"(acc[mi][ni][2]), "+f"(acc[mi][ni][3])
                        : "r"(af[mi][0]), "r"(af[mi][1]), "r"(af[mi][2]), "r"(af[mi][3]),
                          "r"(bf[ni][0]), "r"(bf[ni][1]));
                }
        }
        __syncthreads();
    }

    // epilogue: convert to fp16, store half2 (no scaling; gather folds dinv)
#pragma unroll
    for (int mi = 0; mi < 2; mi++) {
        int m0 = row0 + mBase + mi * 16 + g;
        int m1 = m0 + 8;
#pragma unroll
        for (int ni = 0; ni < 8; ni++) {
            int col = nBase + ni * 8 + 2 * t;
            if (m0 < M) {
                __half2 v = __floats2half2_rn(acc[mi][ni][0], acc[mi][ni][1]);
                *reinterpret_cast<__half2*>(out + (size_t)m0 * BN + col) = v;
            }
            if (m1 < M) {
                __half2 v = __floats2half2_rn(acc[mi][ni][2], acc[mi][ni][3]);
                *reinterpret_cast<__half2*>(out + (size_t)m1 * BN + col) = v;
            }
        }
    }
}

// ---------------------------------------------------------------------------
// Fused gather (fp16 in/out, fp32 accumulate), dinv folded per-source:
//   out[v,:] = act( dinv[v]*( sum_e dinv[src_e]*hs[src_e,:] + dinv[v]*hs[v,:] ) + b )
// Warp per node; degree from offs diff (deg array is consumed by fill).
// ---------------------------------------------------------------------------
__global__ void gather_fused_kernel(
    const __half* __restrict__ hs, const int* __restrict__ csr,
    const int* __restrict__ offs,
    const float* __restrict__ dinv, const float* __restrict__ b,
    __half* __restrict__ out, int n, int relu)
{
    int warp = (blockIdx.x * blockDim.x + threadIdx.x) >> 5;
    int lane = threadIdx.x & 31;
    if (warp >= n) return;

    int start = offs[warp];
    int d     = offs[warp + 1] - start;
    const int c = lane * 4;
    const float dv = dinv[warp];

    float4 acc;
    {
        uint2 raw = *reinterpret_cast<const uint2*>(hs + (size_t)warp * DHC + c);
        float2 f01 = __half22float2(*reinterpret_cast<__half2*>(&raw.x));
        float2 f23 = __half22float2(*reinterpret_cast<__half2*>(&raw.y));
        acc = make_float4(f01.x * dv, f01.y * dv, f23.x * dv, f23.y * dv);
    }

    for (int base = 0; base < d; base += 32) {
        int idx = base + lane;
        int   s  = 0;
        float ds = 0.f;
        if (idx < d) { s = csr[start + idx]; ds = __ldg(&dinv[s]); }
        int m = min(32, d - base);
        for (int j = 0; j < m; j++) {
            int   sj  = __shfl_sync(0xffffffffu, s,  j);
            float dsj = __shfl_sync(0xffffffffu, ds, j);
            uint2 raw = *reinterpret_cast<const uint2*>(hs + (size_t)sj * DHC + c);
            float2 f01 = __half22float2(*reinterpret_cast<__half2*>(&raw.x));
            float2 f23 = __half22float2(*reinterpret_cast<__half2*>(&raw.y));
            acc.x = fmaf(f01.x, dsj, acc.x);
            acc.y = fmaf(f01.y, dsj, acc.y);
            acc.z = fmaf(f23.x, dsj, acc.z);
            acc.w = fmaf(f23.y, dsj, acc.w);
        }
    }

    float4 bv = *reinterpret_cast<const float4*>(b + c);
    float4 r;
    r.x = fmaf(dv, acc.x, bv.x);
    r.y = fmaf(dv, acc.y, bv.y);
    r.z = fmaf(dv, acc.z, bv.z);
    r.w = fmaf(dv, acc.w, bv.w);
    if (relu) {
        r.x = fmaxf(r.x, 0.f); r.y = fmaxf(r.y, 0.f);
        r.z = fmaxf(r.z, 0.f); r.w = fmaxf(r.w, 0.f);
    }
    uint2 o;
    *reinterpret_cast<__half2*>(&o.x) = __floats2half2_rn(r.x, r.y);
    *reinterpret_cast<__half2*>(&o.y) = __floats2half2_rn(r.z, r.w);
    *reinterpret_cast<uint2*>(out + (size_t)warp * DHC + c) = o;
}

// ---------------------------------------------------------------------------
// Decode: out[e] = dot(z[i,:], z[j,:]) — 2 pairs per warp, 16 lanes each.
// ---------------------------------------------------------------------------
__global__ void decode_kernel(const __half* __restrict__ z, const int* __restrict__ eli,
                              float* __restrict__ out, int EL)
{
    int warp  = (blockIdx.x * blockDim.x + threadIdx.x) >> 5;
    int lane  = threadIdx.x & 31;
    int half  = lane >> 4;
    int hl    = lane & 15;
    int nwarp = (gridDim.x * blockDim.x) >> 5;
    const int c = hl * 8;
    for (int e0 = warp * 2; e0 < EL; e0 += nwarp * 2) {
        int e = e0 + half;
        float d = 0.f;
        if (e < EL) {
            int i = __ldg(&eli[e]);
            int j = __ldg(&eli[EL + e]);
            uint4 ra = *reinterpret_cast<const uint4*>(z + (size_t)i * DHC + c);
            uint4 rb = *reinterpret_cast<const uint4*>(z + (size_t)j * DHC + c);
            const __half2* ha = reinterpret_cast<const __half2*>(&ra);
            const __half2* hb = reinterpret_cast<const __half2*>(&rb);
#pragma unroll
            for (int q = 0; q < 4; q++) {
                float2 fa = __half22float2(ha[q]);
                float2 fb = __half22float2(hb[q]);
                d = fmaf(fa.x, fb.x, d);
                d = fmaf(fa.y, fb.y, d);
            }
        }
#pragma unroll
        for (int off = 8; off; off >>= 1)
            d += __shfl_xor_sync(0xffffffff, d, off);
        if (hl == 0 && e < EL) out[e] = d;
    }
}

// ---------------------------------------------------------------------------
extern "C" void kernel_launch(void* const* d_in, const int* in_sizes, int n_in,
                              void* d_out, int out_size)
{
    const float* x  = (const float*)d_in[0];
    const int*   ei = (const int*)  d_in[1];
    const int*   eli= (const int*)  d_in[2];
    const float* W1 = (const float*)d_in[3];
    const float* b1 = (const float*)d_in[4];
    const float* W2 = (const float*)d_in[5];
    const float* b2 = (const float*)d_in[6];
    float* out = (float*)d_out;

    const int DIN = 256;
    int N  = in_sizes[0] / DIN;
    int E  = in_sizes[1] / 2;
    int EL = in_sizes[2] / 2;

    float *p_dinv;
    __half *p_hs, *p_h, *p_z;
    int *p_deg, *p_offs, *p_csr, *p_bsum;
    cudaGetSymbolAddress((void**)&p_dinv, g_dinv);
    cudaGetSymbolAddress((void**)&p_deg,  g_deg);
    cudaGetSymbolAddress((void**)&p_offs, g_offs);
    cudaGetSymbolAddress((void**)&p_csr,  g_csr);
    cudaGetSymbolAddress((void**)&p_bsum, g_bsum);
    cudaGetSymbolAddress((void**)&p_hs,   g_hs);
    cudaGetSymbolAddress((void**)&p_h,    g_h);
    cudaGetSymbolAddress((void**)&p_z,    g_z);

    int gemm_blocks   = (N + 127) / 128;
    int gather_blocks = (N * 32 + 255) / 256;
    int nb = (N + 1023) / 1024;

    // ---- CSR build (trimmed: 5 launches) ----
    cudaMemsetAsync(p_deg, 0, (size_t)N * sizeof(int));
    deg_kernel<<<2048, 256>>>(ei, p_deg, E);
    scan_phase1<<<nb, 1024>>>(p_deg, p_offs, p_bsum, N);
    scan_phase3b<<<nb, 1024>>>(p_offs, p_bsum, nb, p_deg, p_dinv, N);
    fill_kernel<<<2048, 256>>>(ei, p_offs, p_deg, p_csr, E);

    // ---- layer 1 ----
    gemm_tf32_kernel<false><<<gemm_blocks, 256>>>(x, W1, p_hs, N, DIN);
    gather_fused_kernel<<<gather_blocks, 256>>>(p_hs, p_csr, p_offs,
                                                p_dinv, b1, p_h, N, 1);

    // ---- layer 2 ----
    gemm_tf32_kernel<true><<<gemm_blocks, 256>>>(p_h, W2, p_hs, N, DHC);
    gather_fused_kernel<<<gather_blocks, 256>>>(p_hs, p_csr, p_offs,
                                                p_dinv, b2, p_z, N, 0);

    // ---- decode ----
    decode_kernel<<<(EL * 16 + 255) / 256, 256>>>(p_z, eli, out, EL);
}

// round 16
// speedup vs baseline: 1.1591x; 1.1591x over previous
#include <cuda_runtime.h>
#include <cuda_fp16.h>
#include <cstddef>
#include <cstdint>

#define NMAX 100000
#define EMAX 1600000
#define DHC  128

// Scratch (static __device__ arrays; no allocation allowed)
__device__ float  g_dinv[NMAX];
__device__ int    g_deg[NMAX];
__device__ int    g_offs[NMAX + 1];
__device__ int    g_csr[EMAX];
__device__ int    g_bsum[1024];
__device__ __half g_hs[(size_t)NMAX * DHC];
__device__ __half g_h [(size_t)NMAX * DHC];
__device__ __half g_z [(size_t)NMAX * DHC];

// ---------------------------------------------------------------------------
// Degree histogram (int)
// ---------------------------------------------------------------------------
__global__ void deg_kernel(const int* __restrict__ ei, int* __restrict__ deg, int E) {
    int i = blockIdx.x * blockDim.x + threadIdx.x;
    int stride = gridDim.x * blockDim.x;
    for (; i < E; i += stride)
        atomicAdd(&deg[ei[E + i]], 1);
}

// ---------------------------------------------------------------------------
// Scan phase 1: per-block inclusive scan -> exclusive offs + block sums
// ---------------------------------------------------------------------------
__global__ void scan_phase1(const int* __restrict__ deg, int* __restrict__ offs,
                            int* __restrict__ bsum, int n) {
    __shared__ int sh[1024];
    int i = blockIdx.x * 1024 + threadIdx.x;
    int v = (i < n) ? deg[i] : 0;
    sh[threadIdx.x] = v;
    __syncthreads();
    for (int d = 1; d < 1024; d <<= 1) {
        int t = (threadIdx.x >= d) ? sh[threadIdx.x - d] : 0;
        __syncthreads();
        sh[threadIdx.x] += t;
        __syncthreads();
    }
    if (i < n) offs[i] = sh[threadIdx.x] - v;   // exclusive within block
    if (threadIdx.x == 1023) bsum[blockIdx.x] = sh[1023];
}

// ---------------------------------------------------------------------------
// Scan phase 3b: each block REDUNDANTLY scans bsum (nb <= 1024), adds its
// block prefix, emits dinv, and writes offs[n] = E sentinel.
// ---------------------------------------------------------------------------
__global__ void scan_phase3b(int* __restrict__ offs, const int* __restrict__ bsum,
                             int nb, const int* __restrict__ deg,
                             float* __restrict__ dinv, int n) {
    __shared__ int sh[1024];
    int v = (threadIdx.x < nb) ? bsum[threadIdx.x] : 0;
    sh[threadIdx.x] = v;
    __syncthreads();
    for (int d = 1; d < 1024; d <<= 1) {
        int t = (threadIdx.x >= d) ? sh[threadIdx.x - d] : 0;
        __syncthreads();
        sh[threadIdx.x] += t;
        __syncthreads();
    }
    int excl = (blockIdx.x == 0) ? 0 : sh[blockIdx.x - 1];
    int i = blockIdx.x * 1024 + threadIdx.x;
    if (i < n) {
        int o = offs[i] + excl;
        offs[i] = o;
        int dg = deg[i];
        dinv[i] = rsqrtf((float)dg + 1.0f);
        if (i == n - 1) offs[n] = o + dg;
    }
}

// ---------------------------------------------------------------------------
// CSR fill: countdown on deg (deg ends at 0; gather uses offs diffs)
// ---------------------------------------------------------------------------
__global__ void fill_kernel(const int* __restrict__ ei, const int* __restrict__ offs,
                            int* __restrict__ deg, int* __restrict__ csr, int E) {
    int i = blockIdx.x * blockDim.x + threadIdx.x;
    int stride = gridDim.x * blockDim.x;
    for (; i < E; i += stride) {
        int src = ei[i];
        int dst = ei[E + i];
        int pos = offs[dst] + atomicSub(&deg[dst], 1) - 1;
        csr[pos] = src;
    }
}

// ---------------------------------------------------------------------------
// TF32 tensor-core GEMM: out_fp16[r,:] = (A[r,:K] @ W[K,128]) * dinv[r]
// fp32 inputs go through cvt.rna.tf32 (unbiased — truncation is biased and
// fails at K=256). fp16 A (AHALF=true) is exact in tf32: raw bits.
// BM=128 BN=128 BK=16, 256 threads = 8 warps (4x2), warp tile 32x64.
// ---------------------------------------------------------------------------
__device__ __forceinline__ uint32_t f2tf32(float x) {
    uint32_t r;
    asm("cvt.rna.tf32.f32 %0, %1;" : "=r"(r) : "f"(x));
    return r;
}

template<bool AHALF>
__global__ __launch_bounds__(256, 2) void gemm_tf32_kernel(
    const void* __restrict__ Av, const float* __restrict__ W,
    const float* __restrict__ dinv, __half* __restrict__ out,
    int M, int K)
{
    constexpr int BM = 128, BN = 128, BK = 16;
    constexpr int ASTR = BK + 4;   // 20
    constexpr int BSTR = BN + 8;   // 136
    __shared__ uint32_t As[BM * ASTR];
    __shared__ uint32_t Bs[BK * BSTR];

    const int tid  = threadIdx.x;
    const int wid  = tid >> 5;
    const int lane = tid & 31;
    const int g    = lane >> 2;
    const int t    = lane & 3;
    const int warpM = wid >> 1;
    const int warpN = wid & 1;
    const int row0 = blockIdx.x * BM;

    // fp32-A load map: 512 float4/tile (128 rows x 4 float4), 2 per thread
    const int ar0 = tid >> 2;            // 0..63
    const int ac0 = (tid & 3) * 4;       // 0,4,8,12
    const int ar1 = ar0 + 64;            // 64..127
    // fp16-A load map: 256 uint4/tile, 1 per thread
    const int arh = tid >> 1, ach = (tid & 1) * 8;
    // B load map
    const int br0 = wid, br1 = wid + 8;
    const int bc  = lane * 4;

    float acc[2][8][4];
#pragma unroll
    for (int mi = 0; mi < 2; mi++)
#pragma unroll
        for (int ni = 0; ni < 8; ni++)
#pragma unroll
            for (int c = 0; c < 4; c++) acc[mi][ni][c] = 0.0f;

    float4 aPre0, aPre1, bPre0, bPre1;
    uint4  aPreH;
    {
        if (AHALF) {
            const __half* A = (const __half*)Av;
            int r = row0 + arh;
            aPreH = (r < M) ? *reinterpret_cast<const uint4*>(A + (size_t)r * K + ach)
                            : make_uint4(0, 0, 0, 0);
        } else {
            const float* A = (const float*)Av;
            int r = row0 + ar0;
            aPre0 = (r < M) ? *reinterpret_cast<const float4*>(A + (size_t)r * K + ac0)
                            : make_float4(0.f, 0.f, 0.f, 0.f);
            r = row0 + ar1;
            aPre1 = (r < M) ? *reinterpret_cast<const float4*>(A + (size_t)r * K + ac0)
                            : make_float4(0.f, 0.f, 0.f, 0.f);
        }
        bPre0 = *reinterpret_cast<const float4*>(W + (size_t)br0 * BN + bc);
        bPre1 = *reinterpret_cast<const float4*>(W + (size_t)br1 * BN + bc);
    }

    const int mBase = warpM * 32;
    const int nBase = warpN * 64;

    for (int k0 = 0; k0 < K; k0 += BK) {
        if (AHALF) {
            uint32_t* p = &As[arh * ASTR + ach];
            const __half2* hp = reinterpret_cast<const __half2*>(&aPreH);
#pragma unroll
            for (int q = 0; q < 4; q++) {
                float2 f = __half22float2(hp[q]);
                p[2 * q    ] = __float_as_uint(f.x);
                p[2 * q + 1] = __float_as_uint(f.y);
            }
        } else {
            uint32_t* p = &As[ar0 * ASTR + ac0];
            p[0] = f2tf32(aPre0.x); p[1] = f2tf32(aPre0.y);
            p[2] = f2tf32(aPre0.z); p[3] = f2tf32(aPre0.w);
            p = &As[ar1 * ASTR + ac0];
            p[0] = f2tf32(aPre1.x); p[1] = f2tf32(aPre1.y);
            p[2] = f2tf32(aPre1.z); p[3] = f2tf32(aPre1.w);
        }
        {
            uint32_t* p = &Bs[br0 * BSTR + bc];
            p[0] = f2tf32(bPre0.x); p[1] = f2tf32(bPre0.y);
            p[2] = f2tf32(bPre0.z); p[3] = f2tf32(bPre0.w);
            p = &Bs[br1 * BSTR + bc];
            p[0] = f2tf32(bPre1.x); p[1] = f2tf32(bPre1.y);
            p[2] = f2tf32(bPre1.z); p[3] = f2tf32(bPre1.w);
        }
        __syncthreads();

        if (k0 + BK < K) {
            int kn = k0 + BK;
            if (AHALF) {
                const __half* A = (const __half*)Av;
                int r = row0 + arh;
                aPreH = (r < M) ? *reinterpret_cast<const uint4*>(A + (size_t)r * K + kn + ach)
                                : make_uint4(0, 0, 0, 0);
            } else {
                const float* A = (const float*)Av;
                int r = row0 + ar0;
                aPre0 = (r < M) ? *reinterpret_cast<const float4*>(A + (size_t)r * K + kn + ac0)
                                : make_float4(0.f, 0.f, 0.f, 0.f);
                r = row0 + ar1;
                aPre1 = (r < M) ? *reinterpret_cast<const float4*>(A + (size_t)r * K + kn + ac0)
                                : make_float4(0.f, 0.f, 0.f, 0.f);
            }
            bPre0 = *reinterpret_cast<const float4*>(W + (size_t)(kn + br0) * BN + bc);
            bPre1 = *reinterpret_cast<const float4*>(W + (size_t)(kn + br1) * BN + bc);
        }

#pragma unroll
        for (int ks = 0; ks < 2; ks++) {
            const int kb = ks * 8;
            uint32_t af[2][4];
#pragma unroll
            for (int mi = 0; mi < 2; mi++) {
                int m = mBase + mi * 16 + g;
                af[mi][0] = As[(m    ) * ASTR + kb + t];
                af[mi][1] = As[(m + 8) * ASTR + kb + t];
                af[mi][2] = As[(m    ) * ASTR + kb + t + 4];
                af[mi][3] = As[(m + 8) * ASTR + kb + t + 4];
            }
            uint32_t bf[8][2];
#pragma unroll
            for (int ni = 0; ni < 8; ni++) {
                int n = nBase + ni * 8 + g;
                bf[ni][0] = Bs[(kb + t    ) * BSTR + n];
                bf[ni][1] = Bs[(kb + t + 4) * BSTR + n];
            }
#pragma unroll
            for (int mi = 0; mi < 2; mi++)
#pragma unroll
                for (int ni = 0; ni < 8; ni++) {
                    asm volatile(
                        "mma.sync.aligned.m16n8k8.row.col.f32.tf32.tf32.f32 "
                        "{%0,%1,%2,%3}, {%4,%5,%6,%7}, {%8,%9}, {%0,%1,%2,%3};"
                        : "+f"(acc[mi][ni][0]), "+f"(acc[mi][ni][1]),
                          "+f"(acc[mi][ni][2]), "+f"(acc[mi][ni][3])
                        : "r"(af[mi][0]), "r"(af[mi][1]), "r"(af[mi][2]), "r"(af[mi][3]),
                          "r"(bf[ni][0]), "r"(bf[ni][1]));
                }
        }
        __syncthreads();
    }

    // epilogue: scale by dinv[row], convert to fp16, store half2
#pragma unroll
    for (int mi = 0; mi < 2; mi++) {
        int m0 = row0 + mBase + mi * 16 + g;
        int m1 = m0 + 8;
        float s0 = (m0 < M) ? __ldg(&dinv[m0]) : 0.f;
        float s1 = (m1 < M) ? __ldg(&dinv[m1]) : 0.f;
#pragma unroll
        for (int ni = 0; ni < 8; ni++) {
            int col = nBase + ni * 8 + 2 * t;
            if (m0 < M) {
                __half2 v = __floats2half2_rn(acc[mi][ni][0] * s0, acc[mi][ni][1] * s0);
                *reinterpret_cast<__half2*>(out + (size_t)m0 * BN + col) = v;
            }
            if (m1 < M) {
                __half2 v = __floats2half2_rn(acc[mi][ni][2] * s1, acc[mi][ni][3] * s1);
                *reinterpret_cast<__half2*>(out + (size_t)m1 * BN + col) = v;
            }
        }
    }
}

// ---------------------------------------------------------------------------
// Fused gather (fp16 in/out, fp32 accumulate). hs rows are pre-scaled by
// dinv[src], so this is a pure row-sum:
//   out[v,:] = act( dinv[v] * ( sum_e hs[src_e,:] + hs[v,:] ) + b )
// Warp per node; degree from offs diff.
// ---------------------------------------------------------------------------
__global__ void gather_fused_kernel(
    const __half* __restrict__ hs, const int* __restrict__ csr,
    const int* __restrict__ offs,
    const float* __restrict__ dinv, const float* __restrict__ b,
    __half* __restrict__ out, int n, int relu)
{
    int warp = (blockIdx.x * blockDim.x + threadIdx.x) >> 5;
    int lane = threadIdx.x & 31;
    if (warp >= n) return;

    int start = offs[warp];
    int d     = offs[warp + 1] - start;
    const int c = lane * 4;

    float4 acc;
    {
        uint2 raw = *reinterpret_cast<const uint2*>(hs + (size_t)warp * DHC + c);
        float2 f01 = __half22float2(*reinterpret_cast<__half2*>(&raw.x));
        float2 f23 = __half22float2(*reinterpret_cast<__half2*>(&raw.y));
        acc = make_float4(f01.x, f01.y, f23.x, f23.y);
    }

    for (int base = 0; base < d; base += 32) {
        int idx = base + lane;
        int s = (idx < d) ? csr[start + idx] : 0;
        int m = min(32, d - base);
        for (int j = 0; j < m; j++) {
            int sj = __shfl_sync(0xffffffffu, s, j);
            uint2 raw = *reinterpret_cast<const uint2*>(hs + (size_t)sj * DHC + c);
            float2 f01 = __half22float2(*reinterpret_cast<__half2*>(&raw.x));
            float2 f23 = __half22float2(*reinterpret_cast<__half2*>(&raw.y));
            acc.x += f01.x; acc.y += f01.y; acc.z += f23.x; acc.w += f23.y;
        }
    }

    float sc = dinv[warp];
    float4 bv = *reinterpret_cast<const float4*>(b + c);
    float4 r;
    r.x = fmaf(sc, acc.x, bv.x);
    r.y = fmaf(sc, acc.y, bv.y);
    r.z = fmaf(sc, acc.z, bv.z);
    r.w = fmaf(sc, acc.w, bv.w);
    if (relu) {
        r.x = fmaxf(r.x, 0.f); r.y = fmaxf(r.y, 0.f);
        r.z = fmaxf(r.z, 0.f); r.w = fmaxf(r.w, 0.f);
    }
    uint2 o;
    *reinterpret_cast<__half2*>(&o.x) = __floats2half2_rn(r.x, r.y);
    *reinterpret_cast<__half2*>(&o.y) = __floats2half2_rn(r.z, r.w);
    *reinterpret_cast<uint2*>(out + (size_t)warp * DHC + c) = o;
}

// ---------------------------------------------------------------------------
// Decode: out[e] = dot(z[i,:], z[j,:]) — 2 pairs per warp, 16 lanes each.
// ---------------------------------------------------------------------------
__global__ void decode_kernel(const __half* __restrict__ z, const int* __restrict__ eli,
                              float* __restrict__ out, int EL)
{
    int warp  = (blockIdx.x * blockDim.x + threadIdx.x) >> 5;
    int lane  = threadIdx.x & 31;
    int half  = lane >> 4;
    int hl    = lane & 15;
    int nwarp = (gridDim.x * blockDim.x) >> 5;
    const int c = hl * 8;
    for (int e0 = warp * 2; e0 < EL; e0 += nwarp * 2) {
        int e = e0 + half;
        float d = 0.f;
        if (e < EL) {
            int i = __ldg(&eli[e]);
            int j = __ldg(&eli[EL + e]);
            uint4 ra = *reinterpret_cast<const uint4*>(z + (size_t)i * DHC + c);
            uint4 rb = *reinterpret_cast<const uint4*>(z + (size_t)j * DHC + c);
            const __half2* ha = reinterpret_cast<const __half2*>(&ra);
            const __half2* hb = reinterpret_cast<const __half2*>(&rb);
#pragma unroll
            for (int q = 0; q < 4; q++) {
                float2 fa = __half22float2(ha[q]);
                float2 fb = __half22float2(hb[q]);
                d = fmaf(fa.x, fb.x, d);
                d = fmaf(fa.y, fb.y, d);
            }
        }
#pragma unroll
        for (int off = 8; off; off >>= 1)
            d += __shfl_xor_sync(0xffffffff, d, off);
        if (hl == 0 && e < EL) out[e] = d;
    }
}

// ---------------------------------------------------------------------------
extern "C" void kernel_launch(void* const* d_in, const int* in_sizes, int n_in,
                              void* d_out, int out_size)
{
    const float* x  = (const float*)d_in[0];
    const int*   ei = (const int*)  d_in[1];
    const int*   eli= (const int*)  d_in[2];
    const float* W1 = (const float*)d_in[3];
    const float* b1 = (const float*)d_in[4];
    const float* W2 = (const float*)d_in[5];
    const float* b2 = (const float*)d_in[6];
    float* out = (float*)d_out;

    const int DIN = 256;
    int N  = in_sizes[0] / DIN;
    int E  = in_sizes[1] / 2;
    int EL = in_sizes[2] / 2;

    float *p_dinv;
    __half *p_hs, *p_h, *p_z;
    int *p_deg, *p_offs, *p_csr, *p_bsum;
    cudaGetSymbolAddress((void**)&p_dinv, g_dinv);
    cudaGetSymbolAddress((void**)&p_deg,  g_deg);
    cudaGetSymbolAddress((void**)&p_offs, g_offs);
    cudaGetSymbolAddress((void**)&p_csr,  g_csr);
    cudaGetSymbolAddress((void**)&p_bsum, g_bsum);
    cudaGetSymbolAddress((void**)&p_hs,   g_hs);
    cudaGetSymbolAddress((void**)&p_h,    g_h);
    cudaGetSymbolAddress((void**)&p_z,    g_z);

    int gemm_blocks   = (N + 127) / 128;
    int gather_blocks = (N * 32 + 255) / 256;
    int nb = (N + 1023) / 1024;

    // ---- CSR build (trimmed: 5 launches) ----
    cudaMemsetAsync(p_deg, 0, (size_t)N * sizeof(int));
    deg_kernel<<<2048, 256>>>(ei, p_deg, E);
    scan_phase1<<<nb, 1024>>>(p_deg, p_offs, p_bsum, N);
    scan_phase3b<<<nb, 1024>>>(p_offs, p_bsum, nb, p_deg, p_dinv, N);
    fill_kernel<<<2048, 256>>>(ei, p_offs, p_deg, p_csr, E);

    // ---- layer 1 ----
    gemm_tf32_kernel<false><<<gemm_blocks, 256>>>(x, W1, p_dinv, p_hs, N, DIN);
    gather_fused_kernel<<<gather_blocks, 256>>>(p_hs, p_csr, p_offs,
                                                p_dinv, b1, p_h, N, 1);

    // ---- layer 2 ----
    gemm_tf32_kernel<true><<<gemm_blocks, 256>>>(p_h, W2, p_dinv, p_hs, N, DHC);
    gather_fused_kernel<<<gather_blocks, 256>>>(p_hs, p_csr, p_offs,
                                                p_dinv, b2, p_z, N, 0);

    // ---- decode ----
    decode_kernel<<<(EL * 16 + 255) / 256, 256>>>(p_z, eli, out, EL);
}